// round 4
// baseline (speedup 1.0000x reference)
#include <cuda_runtime.h>
#include <cstdint>

#define NN 100000
#define EE 800000
#define D  128
#define MB 128      // nodes per block (fused kernel)
#define AP 132      // A/M smem pitch (floats): conflict-free frag loads
#define WPI 136     // W smem pitch (floats): conflict-free frag loads
#define EPSF 1e-5f
#define SCAN_B 1024
#define NSCANB ((NN + SCAN_B - 1) / SCAN_B)   // 98

// Scratch (__device__ globals; allocation-free rule)
__device__ int g_cnt[NN];        // degrees
__device__ int g_cur[NN];        // fill cursors
__device__ int g_off[NN];        // exclusive offsets (scan1 writes inclusive, scan3 fixes)
__device__ int g_bsum[NSCANB];   // per-block scan sums
__device__ int g_boff[NSCANB];   // exclusive block offsets
__device__ int g_csr[EE];        // CSR src indices

// ---------------------------------------------------------------------------
__global__ void zero_kernel() {
    int idx = blockIdx.x * blockDim.x + threadIdx.x;
    int stride = gridDim.x * blockDim.x;
    for (int i = idx; i < NN; i += stride) { g_cnt[i] = 0; g_cur[i] = 0; }
}

__global__ __launch_bounds__(256) void count_kernel(const int* __restrict__ ei) {
    int e = blockIdx.x * 256 + threadIdx.x;
    if (e < EE) atomicAdd(&g_cnt[ei[EE + e]], 1);
}

// scan1: per-block inclusive scan of 1024 counts -> g_off (inclusive), g_bsum
__global__ __launch_bounds__(SCAN_B) void scan1_kernel() {
    __shared__ int s[SCAN_B];
    int tid = threadIdx.x;
    int i = blockIdx.x * SCAN_B + tid;
    int v = (i < NN) ? g_cnt[i] : 0;
    s[tid] = v;
    __syncthreads();
    #pragma unroll
    for (int d = 1; d < SCAN_B; d <<= 1) {
        int t = (tid >= d) ? s[tid - d] : 0;
        __syncthreads();
        s[tid] += t;
        __syncthreads();
    }
    if (i < NN) g_off[i] = s[tid];
    if (tid == SCAN_B - 1) g_bsum[blockIdx.x] = s[tid];
}

// scan2: exclusive scan of block sums (single block of 128 threads)
__global__ __launch_bounds__(128) void scan2_kernel() {
    __shared__ int s[128];
    int tid = threadIdx.x;
    int v = (tid < NSCANB) ? g_bsum[tid] : 0;
    s[tid] = v;
    __syncthreads();
    #pragma unroll
    for (int d = 1; d < 128; d <<= 1) {
        int t = (tid >= d) ? s[tid - d] : 0;
        __syncthreads();
        s[tid] += t;
        __syncthreads();
    }
    if (tid < NSCANB) g_boff[tid] = s[tid] - v;  // exclusive
}

// scan3: g_off[i] = inclusive - cnt + block_offset  -> exclusive global offset
__global__ __launch_bounds__(SCAN_B) void scan3_kernel() {
    int i = blockIdx.x * SCAN_B + threadIdx.x;
    if (i < NN) g_off[i] = g_off[i] - g_cnt[i] + g_boff[blockIdx.x];
}

__global__ __launch_bounds__(256) void fill_kernel(const int* __restrict__ ei) {
    int e = blockIdx.x * 256 + threadIdx.x;
    if (e >= EE) return;
    int s = ei[e];
    int d = ei[EE + e];
    int pos = atomicAdd(&g_cur[d], 1);
    g_csr[g_off[d] + pos] = s;
}

// ---------------------------------------------------------------------------
// Fused kernel: CSR gather-mean -> smem, x -> smem, dual tf32 MMA, bias+ReLU+LN
// ---------------------------------------------------------------------------
__device__ __forceinline__ uint32_t f2tf32(float f) {
    uint32_t r;
    asm("cvt.rna.tf32.f32 %0, %1;" : "=r"(r) : "f"(f));
    return r;
}

extern __shared__ float smem_f[];

__global__ __launch_bounds__(256, 1) void fused_kernel(
    const float* __restrict__ x,  const float* __restrict__ Ws,
    const float* __restrict__ Wn, const float* __restrict__ bias,
    const float* __restrict__ gamma, const float* __restrict__ beta,
    float* __restrict__ out)
{
    float* As     = smem_f;                 // [MB][AP]  tf32(x)
    float* Ms     = As + MB * AP;           // [MB][AP]  tf32(neigh_mean)
    float* Bsm    = Ms + MB * AP;           // [D][WPI]  k-major weights
    float* red_s  = Bsm + D * WPI;          // [MB][2]
    float* red_s2 = red_s + MB * 2;         // [MB][2]
    float* cbuf   = red_s2 + MB * 2;        // bias | gamma | beta  [3*D]

    const int tid  = threadIdx.x;
    const int base = blockIdx.x * MB;
    const int lane = tid & 31;
    const int wid  = tid >> 5;
    const int wm   = wid & 3;
    const int wn   = wid >> 2;
    const int g    = lane >> 2;
    const int tg   = lane & 3;

    if (tid < D) {
        cbuf[tid]         = bias[tid];
        cbuf[D + tid]     = gamma[tid];
        cbuf[2 * D + tid] = beta[tid];
    }

    // Stage As = tf32(x tile)
    const float4* x4 = (const float4*)x;
    for (int idx = tid; idx < MB * (D / 4); idx += 256) {
        int nl = idx >> 5, k4 = idx & 31;
        int n = base + nl;
        float4 v = make_float4(0.f, 0.f, 0.f, 0.f);
        if (n < NN) v = x4[(size_t)n * 32 + k4];
        float4 c;
        c.x = __uint_as_float(f2tf32(v.x));
        c.y = __uint_as_float(f2tf32(v.y));
        c.z = __uint_as_float(f2tf32(v.z));
        c.w = __uint_as_float(f2tf32(v.w));
        *(float4*)(As + nl * AP + k4 * 4) = c;
    }

    // Stage Bsm = tf32(Ws) transposed
    for (int idx = tid; idx < D * D; idx += 256) {
        int o = idx >> 7, k = idx & (D - 1);
        Bsm[k * WPI + o] = __uint_as_float(f2tf32(Ws[idx]));
    }

    // CSR gather-mean: warp handles 16 nodes; 32 lanes x float4 = one row
    #pragma unroll 1
    for (int u = 0; u < MB / 8; u++) {
        int nl = wid * (MB / 8) + u;
        int n = base + nl;
        float4 a4 = make_float4(0.f, 0.f, 0.f, 0.f);
        int off = 0, deg = 0;
        if (n < NN) { off = g_off[n]; deg = g_cnt[n]; }
        int end = off + deg;
        int j = off;
        for (; j + 1 < end; j += 2) {
            int s0 = g_csr[j], s1 = g_csr[j + 1];
            float4 v0 = x4[(size_t)s0 * 32 + lane];
            float4 v1 = x4[(size_t)s1 * 32 + lane];
            a4.x += v0.x + v1.x; a4.y += v0.y + v1.y;
            a4.z += v0.z + v1.z; a4.w += v0.w + v1.w;
        }
        if (j < end) {
            float4 v = x4[(size_t)g_csr[j] * 32 + lane];
            a4.x += v.x; a4.y += v.y; a4.z += v.z; a4.w += v.w;
        }
        float r = 1.f / fmaxf((float)deg, 1.f);
        float4 c;
        c.x = __uint_as_float(f2tf32(a4.x * r));
        c.y = __uint_as_float(f2tf32(a4.y * r));
        c.z = __uint_as_float(f2tf32(a4.z * r));
        c.w = __uint_as_float(f2tf32(a4.w * r));
        *(float4*)(Ms + nl * AP + lane * 4) = c;
    }
    __syncthreads();

    float acc[2][8][4];
    #pragma unroll
    for (int t = 0; t < 2; t++)
        #pragma unroll
        for (int j = 0; j < 8; j++)
            #pragma unroll
            for (int e = 0; e < 4; e++) acc[t][j][e] = 0.f;

    // Two MMA phases: phase0 = As x Ws, phase1 = Ms x Wn
    #pragma unroll 1
    for (int phase = 0; phase < 2; phase++) {
        if (phase == 1) {
            __syncthreads();
            for (int idx = tid; idx < D * D; idx += 256) {
                int o = idx >> 7, k = idx & (D - 1);
                Bsm[k * WPI + o] = __uint_as_float(f2tf32(Wn[idx]));
            }
            __syncthreads();
        }
        const float* Am = phase ? Ms : As;
        #pragma unroll
        for (int ks = 0; ks < 16; ks++) {
            const int kc = ks * 8;
            uint32_t b[8][2];
            #pragma unroll
            for (int j = 0; j < 8; j++) {
                b[j][0] = __float_as_uint(Bsm[(kc + tg)     * WPI + wn * 64 + j * 8 + g]);
                b[j][1] = __float_as_uint(Bsm[(kc + tg + 4) * WPI + wn * 64 + j * 8 + g]);
            }
            #pragma unroll
            for (int t = 0; t < 2; t++) {
                const int r0 = wm * 32 + t * 16 + g;
                uint32_t a0 = __float_as_uint(Am[r0       * AP + kc + tg]);
                uint32_t a1 = __float_as_uint(Am[(r0 + 8) * AP + kc + tg]);
                uint32_t a2 = __float_as_uint(Am[r0       * AP + kc + tg + 4]);
                uint32_t a3 = __float_as_uint(Am[(r0 + 8) * AP + kc + tg + 4]);
                #pragma unroll
                for (int j = 0; j < 8; j++) {
                    asm volatile(
                        "mma.sync.aligned.m16n8k8.row.col.f32.tf32.tf32.f32 "
                        "{%0,%1,%2,%3}, {%4,%5,%6,%7}, {%8,%9}, {%0,%1,%2,%3};"
                        : "+f"(acc[t][j][0]), "+f"(acc[t][j][1]),
                          "+f"(acc[t][j][2]), "+f"(acc[t][j][3])
                        : "r"(a0), "r"(a1), "r"(a2), "r"(a3),
                          "r"(b[j][0]), "r"(b[j][1]));
                }
            }
        }
    }

    // ---- Epilogue: bias + ReLU + LayerNorm ----
    #pragma unroll
    for (int t = 0; t < 2; t++) {
        #pragma unroll
        for (int h = 0; h < 2; h++) {
            float s = 0.f, s2 = 0.f;
            #pragma unroll
            for (int j = 0; j < 8; j++) {
                #pragma unroll
                for (int e = 0; e < 2; e++) {
                    int col = wn * 64 + j * 8 + tg * 2 + e;
                    float v = fmaxf(acc[t][j][2 * h + e] + cbuf[col], 0.f);
                    acc[t][j][2 * h + e] = v;
                    s += v; s2 += v * v;
                }
            }
            s  += __shfl_xor_sync(0xffffffffu, s, 1);
            s  += __shfl_xor_sync(0xffffffffu, s, 2);
            s2 += __shfl_xor_sync(0xffffffffu, s2, 1);
            s2 += __shfl_xor_sync(0xffffffffu, s2, 2);
            if (tg == 0) {
                int row = wm * 32 + t * 16 + h * 8 + g;
                red_s [row * 2 + wn] = s;
                red_s2[row * 2 + wn] = s2;
            }
        }
    }
    __syncthreads();

    #pragma unroll
    for (int t = 0; t < 2; t++) {
        #pragma unroll
        for (int h = 0; h < 2; h++) {
            int row = wm * 32 + t * 16 + h * 8 + g;
            float s  = red_s [row * 2] + red_s [row * 2 + 1];
            float s2 = red_s2[row * 2] + red_s2[row * 2 + 1];
            float mean = s * (1.f / D);
            float var  = s2 * (1.f / D) - mean * mean;
            float rstd = rsqrtf(var + EPSF);
            int n = base + row;
            if (n < NN) {
                #pragma unroll
                for (int j = 0; j < 8; j++) {
                    int col = wn * 64 + j * 8 + tg * 2;
                    float2 o2;
                    o2.x = (acc[t][j][2 * h + 0] - mean) * rstd * cbuf[D + col]     + cbuf[2 * D + col];
                    o2.y = (acc[t][j][2 * h + 1] - mean) * rstd * cbuf[D + col + 1] + cbuf[2 * D + col + 1];
                    *(float2*)(out + (size_t)n * D + col) = o2;
                }
            }
        }
    }
}

// ---------------------------------------------------------------------------
extern "C" void kernel_launch(void* const* d_in, const int* in_sizes, int n_in,
                              void* d_out, int out_size) {
    const float* x     = (const float*)d_in[0];
    const int*   ei    = (const int*)d_in[1];
    const float* Ws    = (const float*)d_in[2];
    const float* Wn    = (const float*)d_in[3];
    const float* bias  = (const float*)d_in[4];
    const float* gamma = (const float*)d_in[5];
    const float* beta  = (const float*)d_in[6];
    float*       out   = (float*)d_out;

    size_t smem = (size_t)(2 * MB * AP + D * WPI + MB * 2 * 2 + 3 * D) * sizeof(float); // ~208 KB
    cudaFuncSetAttribute(fused_kernel,
                         cudaFuncAttributeMaxDynamicSharedMemorySize, (int)smem);

    zero_kernel<<<196, 512>>>();
    count_kernel<<<(EE + 255) / 256, 256>>>(ei);
    scan1_kernel<<<NSCANB, SCAN_B>>>();
    scan2_kernel<<<1, 128>>>();
    scan3_kernel<<<NSCANB, SCAN_B>>>();
    fill_kernel<<<(EE + 255) / 256, 256>>>(ei);

    int grid = (NN + MB - 1) / MB;
    fused_kernel<<<grid, 256, smem>>>(x, Ws, Wn, bias, gamma, beta, out);
}

// round 5
// speedup vs baseline: 1.3018x; 1.3018x over previous
#include <cuda_runtime.h>
#include <cstdint>

#define NN 100000
#define EE 800000
#define D  128
#define MB 128      // nodes per block (fused kernel)
#define AP 132      // A/M smem pitch (floats): conflict-free frag loads
#define WPI 136     // W smem pitch (floats): conflict-free frag loads
#define CAP 48      // max tracked in-degree (P(overflow) ~ 1e-20; guarded)
#define EPSF 1e-5f

// Scratch (__device__ globals; allocation-free rule)
__device__ int g_cnt[NN];                                  // degrees (doubles as fill cursor)
__device__ __align__(16) int g_csr[(size_t)NN * CAP];      // bucketed src lists
__device__ __align__(16) float g_mean[(size_t)NN * D];     // neighbor means

// ---------------------------------------------------------------------------
__global__ void zero_kernel() {
    int i = blockIdx.x * blockDim.x + threadIdx.x;
    if (i < NN) g_cnt[i] = 0;
}

// fill: one thread per edge; cursor = atomic degree count
__global__ __launch_bounds__(256) void fill_kernel(const int* __restrict__ ei) {
    int e = blockIdx.x * 256 + threadIdx.x;
    if (e >= EE) return;
    int s = ei[e];
    int d = ei[EE + e];
    int p = atomicAdd(&g_cnt[d], 1);
    if (p < CAP) g_csr[(size_t)d * CAP + p] = s;
}

// gather: one warp per node; lane owns one float4 (16B) of the 512B row.
// 4-wide unrolled independent loads -> MLP>=4 per warp; huge warp count
// (100k) hides L2 latency.
__global__ __launch_bounds__(256) void gather_kernel(const float* __restrict__ x) {
    int n    = (blockIdx.x * 256 + threadIdx.x) >> 5;
    int lane = threadIdx.x & 31;
    if (n >= NN) return;

    int cnt = g_cnt[n];
    int m   = min(cnt, CAP);
    const float4* x4  = (const float4*)x;
    const int*    lst = g_csr + (size_t)n * CAP;

    float4 a = make_float4(0.f, 0.f, 0.f, 0.f);
    int j = 0;
    for (; j + 4 <= m; j += 4) {
        int4 s4 = *(const int4*)(lst + j);        // 16B-aligned (CAP%4==0)
        float4 v0 = x4[(size_t)s4.x * 32 + lane];
        float4 v1 = x4[(size_t)s4.y * 32 + lane];
        float4 v2 = x4[(size_t)s4.z * 32 + lane];
        float4 v3 = x4[(size_t)s4.w * 32 + lane];
        a.x += (v0.x + v1.x) + (v2.x + v3.x);
        a.y += (v0.y + v1.y) + (v2.y + v3.y);
        a.z += (v0.z + v1.z) + (v2.z + v3.z);
        a.w += (v0.w + v1.w) + (v2.w + v3.w);
    }
    for (; j < m; j++) {
        float4 v = x4[(size_t)lst[j] * 32 + lane];
        a.x += v.x; a.y += v.y; a.z += v.z; a.w += v.w;
    }
    float r = 1.f / fmaxf((float)cnt, 1.f);
    a.x *= r; a.y *= r; a.z *= r; a.w *= r;
    ((float4*)g_mean)[(size_t)n * 32 + lane] = a;
}

// ---------------------------------------------------------------------------
// Fused kernel: stage tf32(x) + tf32(g_mean) + weights, dual MMA, bias+ReLU+LN
// ---------------------------------------------------------------------------
__device__ __forceinline__ uint32_t f2tf32(float f) {
    uint32_t r;
    asm("cvt.rna.tf32.f32 %0, %1;" : "=r"(r) : "f"(f));
    return r;
}

extern __shared__ float smem_f[];

__global__ __launch_bounds__(256, 1) void fused_kernel(
    const float* __restrict__ x,  const float* __restrict__ Ws,
    const float* __restrict__ Wn, const float* __restrict__ bias,
    const float* __restrict__ gamma, const float* __restrict__ beta,
    float* __restrict__ out)
{
    float* As     = smem_f;                 // [MB][AP]  tf32(x)
    float* Ms     = As + MB * AP;           // [MB][AP]  tf32(neigh_mean)
    float* Bsm    = Ms + MB * AP;           // [D][WPI]  k-major weights
    float* red_s  = Bsm + D * WPI;          // [MB][2]
    float* red_s2 = red_s + MB * 2;         // [MB][2]
    float* cbuf   = red_s2 + MB * 2;        // bias | gamma | beta  [3*D]

    const int tid  = threadIdx.x;
    const int base = blockIdx.x * MB;
    const int lane = tid & 31;
    const int wid  = tid >> 5;
    const int wm   = wid & 3;
    const int wn   = wid >> 2;
    const int g    = lane >> 2;
    const int tg   = lane & 3;

    if (tid < D) {
        cbuf[tid]         = bias[tid];
        cbuf[D + tid]     = gamma[tid];
        cbuf[2 * D + tid] = beta[tid];
    }

    // Stage As = tf32(x tile), Ms = tf32(mean tile)
    const float4* x4 = (const float4*)x;
    const float4* m4 = (const float4*)g_mean;
    for (int idx = tid; idx < MB * (D / 4); idx += 256) {
        int nl = idx >> 5, k4 = idx & 31;
        int n = base + nl;
        float4 v = make_float4(0.f, 0.f, 0.f, 0.f);
        float4 u = v;
        if (n < NN) {
            v = x4[(size_t)n * 32 + k4];
            u = m4[(size_t)n * 32 + k4];
        }
        float4 cv, cu;
        cv.x = __uint_as_float(f2tf32(v.x)); cv.y = __uint_as_float(f2tf32(v.y));
        cv.z = __uint_as_float(f2tf32(v.z)); cv.w = __uint_as_float(f2tf32(v.w));
        cu.x = __uint_as_float(f2tf32(u.x)); cu.y = __uint_as_float(f2tf32(u.y));
        cu.z = __uint_as_float(f2tf32(u.z)); cu.w = __uint_as_float(f2tf32(u.w));
        *(float4*)(As + nl * AP + k4 * 4) = cv;
        *(float4*)(Ms + nl * AP + k4 * 4) = cu;
    }

    // Stage Bsm = tf32(Ws) transposed (phase 0 weights)
    for (int idx = tid; idx < D * D; idx += 256) {
        int o = idx >> 7, k = idx & (D - 1);
        Bsm[k * WPI + o] = __uint_as_float(f2tf32(Ws[idx]));
    }
    __syncthreads();

    float acc[2][8][4];
    #pragma unroll
    for (int t = 0; t < 2; t++)
        #pragma unroll
        for (int j = 0; j < 8; j++)
            #pragma unroll
            for (int e = 0; e < 4; e++) acc[t][j][e] = 0.f;

    // Two MMA phases: phase0 = As x Ws, phase1 = Ms x Wn
    #pragma unroll 1
    for (int phase = 0; phase < 2; phase++) {
        if (phase == 1) {
            __syncthreads();
            for (int idx = tid; idx < D * D; idx += 256) {
                int o = idx >> 7, k = idx & (D - 1);
                Bsm[k * WPI + o] = __uint_as_float(f2tf32(Wn[idx]));
            }
            __syncthreads();
        }
        const float* Am = phase ? Ms : As;
        #pragma unroll
        for (int ks = 0; ks < 16; ks++) {
            const int kc = ks * 8;
            uint32_t b[8][2];
            #pragma unroll
            for (int j = 0; j < 8; j++) {
                b[j][0] = __float_as_uint(Bsm[(kc + tg)     * WPI + wn * 64 + j * 8 + g]);
                b[j][1] = __float_as_uint(Bsm[(kc + tg + 4) * WPI + wn * 64 + j * 8 + g]);
            }
            #pragma unroll
            for (int t = 0; t < 2; t++) {
                const int r0 = wm * 32 + t * 16 + g;
                uint32_t a0 = __float_as_uint(Am[r0       * AP + kc + tg]);
                uint32_t a1 = __float_as_uint(Am[(r0 + 8) * AP + kc + tg]);
                uint32_t a2 = __float_as_uint(Am[r0       * AP + kc + tg + 4]);
                uint32_t a3 = __float_as_uint(Am[(r0 + 8) * AP + kc + tg + 4]);
                #pragma unroll
                for (int j = 0; j < 8; j++) {
                    asm volatile(
                        "mma.sync.aligned.m16n8k8.row.col.f32.tf32.tf32.f32 "
                        "{%0,%1,%2,%3}, {%4,%5,%6,%7}, {%8,%9}, {%0,%1,%2,%3};"
                        : "+f"(acc[t][j][0]), "+f"(acc[t][j][1]),
                          "+f"(acc[t][j][2]), "+f"(acc[t][j][3])
                        : "r"(a0), "r"(a1), "r"(a2), "r"(a3),
                          "r"(b[j][0]), "r"(b[j][1]));
                }
            }
        }
    }

    // ---- Epilogue: bias + ReLU + LayerNorm ----
    #pragma unroll
    for (int t = 0; t < 2; t++) {
        #pragma unroll
        for (int h = 0; h < 2; h++) {
            float s = 0.f, s2 = 0.f;
            #pragma unroll
            for (int j = 0; j < 8; j++) {
                #pragma unroll
                for (int e = 0; e < 2; e++) {
                    int col = wn * 64 + j * 8 + tg * 2 + e;
                    float v = fmaxf(acc[t][j][2 * h + e] + cbuf[col], 0.f);
                    acc[t][j][2 * h + e] = v;
                    s += v; s2 += v * v;
                }
            }
            s  += __shfl_xor_sync(0xffffffffu, s, 1);
            s  += __shfl_xor_sync(0xffffffffu, s, 2);
            s2 += __shfl_xor_sync(0xffffffffu, s2, 1);
            s2 += __shfl_xor_sync(0xffffffffu, s2, 2);
            if (tg == 0) {
                int row = wm * 32 + t * 16 + h * 8 + g;
                red_s [row * 2 + wn] = s;
                red_s2[row * 2 + wn] = s2;
            }
        }
    }
    __syncthreads();

    #pragma unroll
    for (int t = 0; t < 2; t++) {
        #pragma unroll
        for (int h = 0; h < 2; h++) {
            int row = wm * 32 + t * 16 + h * 8 + g;
            float s  = red_s [row * 2] + red_s [row * 2 + 1];
            float s2 = red_s2[row * 2] + red_s2[row * 2 + 1];
            float mean = s * (1.f / D);
            float var  = s2 * (1.f / D) - mean * mean;
            float rstd = rsqrtf(var + EPSF);
            int n = base + row;
            if (n < NN) {
                #pragma unroll
                for (int j = 0; j < 8; j++) {
                    int col = wn * 64 + j * 8 + tg * 2;
                    float2 o2;
                    o2.x = (acc[t][j][2 * h + 0] - mean) * rstd * cbuf[D + col]     + cbuf[2 * D + col];
                    o2.y = (acc[t][j][2 * h + 1] - mean) * rstd * cbuf[D + col + 1] + cbuf[2 * D + col + 1];
                    *(float2*)(out + (size_t)n * D + col) = o2;
                }
            }
        }
    }
}

// ---------------------------------------------------------------------------
extern "C" void kernel_launch(void* const* d_in, const int* in_sizes, int n_in,
                              void* d_out, int out_size) {
    const float* x     = (const float*)d_in[0];
    const int*   ei    = (const int*)d_in[1];
    const float* Ws    = (const float*)d_in[2];
    const float* Wn    = (const float*)d_in[3];
    const float* bias  = (const float*)d_in[4];
    const float* gamma = (const float*)d_in[5];
    const float* beta  = (const float*)d_in[6];
    float*       out   = (float*)d_out;

    size_t smem = (size_t)(2 * MB * AP + D * WPI + MB * 2 * 2 + 3 * D) * sizeof(float);
    cudaFuncSetAttribute(fused_kernel,
                         cudaFuncAttributeMaxDynamicSharedMemorySize, (int)smem);

    zero_kernel<<<(NN + 511) / 512, 512>>>();
    fill_kernel<<<(EE + 255) / 256, 256>>>(ei);
    gather_kernel<<<(NN * 32 + 255) / 256, 256>>>(x);

    int grid = (NN + MB - 1) / MB;
    fused_kernel<<<grid, 256, smem>>>(x, Ws, Wn, bias, gamma, beta, out);
}

// round 6
// speedup vs baseline: 1.3550x; 1.0408x over previous
#include <cuda_runtime.h>
#include <cstdint>

#define NN 100000
#define EE 800000
#define D  128
#define MB 64        // nodes per block (fused kernel)
#define PA2 68       // A pitch in float2 (64 + 4 pad): frag banks g*4+tg
#define PB2 132      // B pitch in float2 (128 + 4 pad): frag banks tg*4+g
#define CAP 48
#define EPSF 1e-5f

// Scratch (__device__ globals; allocation-free rule)
__device__ int g_cnt[NN];
__device__ __align__(16) int g_csr[(size_t)NN * CAP];
__device__ __align__(16) float g_mean[(size_t)NN * D];

// ---------------------------------------------------------------------------
__global__ void zero_kernel() {
    int i = blockIdx.x * blockDim.x + threadIdx.x;
    if (i < NN) g_cnt[i] = 0;
}

__global__ __launch_bounds__(256) void fill_kernel(const int* __restrict__ ei) {
    int e = blockIdx.x * 256 + threadIdx.x;
    if (e >= EE) return;
    int s = ei[e];
    int d = ei[EE + e];
    int p = atomicAdd(&g_cnt[d], 1);
    if (p < CAP) g_csr[(size_t)d * CAP + p] = s;
}

__global__ __launch_bounds__(256) void gather_kernel(const float* __restrict__ x) {
    int n    = (blockIdx.x * 256 + threadIdx.x) >> 5;
    int lane = threadIdx.x & 31;
    if (n >= NN) return;

    int cnt = g_cnt[n];
    int m   = min(cnt, CAP);
    const float4* x4  = (const float4*)x;
    const int*    lst = g_csr + (size_t)n * CAP;

    float4 a = make_float4(0.f, 0.f, 0.f, 0.f);
    int j = 0;
    for (; j + 4 <= m; j += 4) {
        int4 s4 = *(const int4*)(lst + j);
        float4 v0 = x4[(size_t)s4.x * 32 + lane];
        float4 v1 = x4[(size_t)s4.y * 32 + lane];
        float4 v2 = x4[(size_t)s4.z * 32 + lane];
        float4 v3 = x4[(size_t)s4.w * 32 + lane];
        a.x += (v0.x + v1.x) + (v2.x + v3.x);
        a.y += (v0.y + v1.y) + (v2.y + v3.y);
        a.z += (v0.z + v1.z) + (v2.z + v3.z);
        a.w += (v0.w + v1.w) + (v2.w + v3.w);
    }
    for (; j < m; j++) {
        float4 v = x4[(size_t)lst[j] * 32 + lane];
        a.x += v.x; a.y += v.y; a.z += v.z; a.w += v.w;
    }
    float r = 1.f / fmaxf((float)cnt, 1.f);
    a.x *= r; a.y *= r; a.z *= r; a.w *= r;
    ((float4*)g_mean)[(size_t)n * 32 + lane] = a;
}

// ---------------------------------------------------------------------------
__device__ __forceinline__ uint32_t f2tf32(float f) {
    uint32_t r;
    asm("cvt.rna.tf32.f32 %0, %1;" : "=r"(r) : "f"(f));
    return r;
}

extern __shared__ float smem_f[];

// smem layout (floats):
//   Ap : 64 rows x 136  (pairs (k,k+4) as float2, pitch PA2=68 f2)   8704
//   Bp : 64 pr   x 264  (pr = ks*4+tg; pairs (k,k+4); pitch 132 f2) 16896
//   red_s[64][4], red_s2[64][4], cbuf[384]
__global__ __launch_bounds__(256, 2) void fused_kernel(
    const float* __restrict__ x,  const float* __restrict__ Ws,
    const float* __restrict__ Wn, const float* __restrict__ bias,
    const float* __restrict__ gamma, const float* __restrict__ beta,
    float* __restrict__ out)
{
    float* Ap     = smem_f;
    float* Bp     = Ap + MB * (2 * PA2);       // 8704
    float* red_s  = Bp + 64 * (2 * PB2);       // +16896
    float* red_s2 = red_s + MB * 4;
    float* cbuf   = red_s2 + MB * 4;

    const int tid  = threadIdx.x;
    const int base = blockIdx.x * MB;
    const int lane = tid & 31;
    const int wid  = tid >> 5;
    const int wm   = wid & 1;        // row half: wm*32
    const int wn   = wid >> 1;       // col quarter: wn*32
    const int g    = lane >> 2;      // 0..7
    const int tg   = lane & 3;       // 0..3

    if (tid < D) {
        cbuf[tid]         = bias[tid];
        cbuf[D + tid]     = gamma[tid];
        cbuf[2 * D + tid] = beta[tid];
    }

    // Staging decompositions (pair-interleaved writes, coalesced reads)
    const int a_rl = tid & 7;           // row low
    const int a_cl = (tid >> 3) & 3;    // c low (float4 index)
    const int a_rg = tid >> 5;          // row mid (0..7)

    float acc[2][4][4];
    #pragma unroll
    for (int t = 0; t < 2; t++)
        #pragma unroll
        for (int j = 0; j < 4; j++)
            #pragma unroll
            for (int e = 0; e < 4; e++) acc[t][j][e] = 0.f;

    const float2* Ap2 = (const float2*)Ap;
    const float2* Bp2 = (const float2*)Bp;

    #pragma unroll 1
    for (int phase = 0; phase < 2; phase++) {
        if (phase == 1) __syncthreads();   // MMA reads of phase 0 done

        // ---- stage A tile (x or mean), tf32, pair-interleaved ----
        const float4* src4 = phase ? (const float4*)g_mean : (const float4*)x;
        #pragma unroll
        for (int it = 0; it < 8; it++) {
            int row = a_rl + 8 * a_rg;
            int c   = a_cl + 4 * it;
            int n   = base + row;
            float4 v = make_float4(0.f, 0.f, 0.f, 0.f);
            if (n < NN) v = src4[(size_t)n * 32 + c];
            int prb = (c >> 1) * 4;      // pair-row base
            int sl  = c & 1;             // slot within float2
            float* dst = Ap + row * (2 * PA2);
            dst[(prb + 0) * 2 + sl] = __uint_as_float(f2tf32(v.x));
            dst[(prb + 1) * 2 + sl] = __uint_as_float(f2tf32(v.y));
            dst[(prb + 2) * 2 + sl] = __uint_as_float(f2tf32(v.z));
            dst[(prb + 3) * 2 + sl] = __uint_as_float(f2tf32(v.w));
        }

        // ---- stage B (Ws or Wn), tf32, pair-interleaved: Bp[pr][col] ----
        const float4* W4 = (const float4*)(phase ? Wn : Ws);
        #pragma unroll
        for (int it = 0; it < 16; it++) {
            int col = a_rl + 8 * a_rg + 64 * (it >> 3);
            int c   = a_cl + 4 * (it & 7);
            float4 v = W4[(size_t)col * 32 + c];
            int prb = (c >> 1) * 4;
            int sl  = c & 1;
            float* dst = Bp + col * 2 + sl;
            dst[(prb + 0) * (2 * PB2)] = __uint_as_float(f2tf32(v.x));
            dst[(prb + 1) * (2 * PB2)] = __uint_as_float(f2tf32(v.y));
            dst[(prb + 2) * (2 * PB2)] = __uint_as_float(f2tf32(v.z));
            dst[(prb + 3) * (2 * PB2)] = __uint_as_float(f2tf32(v.w));
        }
        __syncthreads();

        // ---- MMA mainloop: 16 k-steps, 8 LDS.64 + 8 MMA each ----
        #pragma unroll
        for (int ks = 0; ks < 16; ks++) {
            float2 bb[4];
            #pragma unroll
            for (int j = 0; j < 4; j++)
                bb[j] = Bp2[(ks * 4 + tg) * PB2 + wn * 32 + j * 8 + g];
            #pragma unroll
            for (int t = 0; t < 2; t++) {
                const int r0 = wm * 32 + t * 16 + g;
                float2 a02 = Ap2[r0 * PA2       + ks * 4 + tg];
                float2 a13 = Ap2[(r0 + 8) * PA2 + ks * 4 + tg];
                uint32_t ua0 = __float_as_uint(a02.x);
                uint32_t ua1 = __float_as_uint(a13.x);
                uint32_t ua2 = __float_as_uint(a02.y);
                uint32_t ua3 = __float_as_uint(a13.y);
                #pragma unroll
                for (int j = 0; j < 4; j++) {
                    asm volatile(
                        "mma.sync.aligned.m16n8k8.row.col.f32.tf32.tf32.f32 "
                        "{%0,%1,%2,%3}, {%4,%5,%6,%7}, {%8,%9}, {%0,%1,%2,%3};"
                        : "+f"(acc[t][j][0]), "+f"(acc[t][j][1]),
                          "+f"(acc[t][j][2]), "+f"(acc[t][j][3])
                        : "r"(ua0), "r"(ua1), "r"(ua2), "r"(ua3),
                          "r"(__float_as_uint(bb[j].x)), "r"(__float_as_uint(bb[j].y)));
                }
            }
        }
    }

    // ---- Epilogue: bias + ReLU + LayerNorm ----
    #pragma unroll
    for (int t = 0; t < 2; t++) {
        #pragma unroll
        for (int h = 0; h < 2; h++) {
            float s = 0.f, s2 = 0.f;
            #pragma unroll
            for (int j = 0; j < 4; j++) {
                #pragma unroll
                for (int e = 0; e < 2; e++) {
                    int col = wn * 32 + j * 8 + tg * 2 + e;
                    float v = fmaxf(acc[t][j][2 * h + e] + cbuf[col], 0.f);
                    acc[t][j][2 * h + e] = v;
                    s += v; s2 += v * v;
                }
            }
            s  += __shfl_xor_sync(0xffffffffu, s, 1);
            s  += __shfl_xor_sync(0xffffffffu, s, 2);
            s2 += __shfl_xor_sync(0xffffffffu, s2, 1);
            s2 += __shfl_xor_sync(0xffffffffu, s2, 2);
            if (tg == 0) {
                int row = wm * 32 + t * 16 + h * 8 + g;
                red_s [row * 4 + wn] = s;
                red_s2[row * 4 + wn] = s2;
            }
        }
    }
    __syncthreads();

    #pragma unroll
    for (int t = 0; t < 2; t++) {
        #pragma unroll
        for (int h = 0; h < 2; h++) {
            int row = wm * 32 + t * 16 + h * 8 + g;
            float s  = red_s [row * 4] + red_s [row * 4 + 1]
                     + red_s [row * 4 + 2] + red_s [row * 4 + 3];
            float s2 = red_s2[row * 4] + red_s2[row * 4 + 1]
                     + red_s2[row * 4 + 2] + red_s2[row * 4 + 3];
            float mean = s * (1.f / D);
            float var  = s2 * (1.f / D) - mean * mean;
            float rstd = rsqrtf(var + EPSF);
            int n = base + row;
            if (n < NN) {
                #pragma unroll
                for (int j = 0; j < 4; j++) {
                    int col = wn * 32 + j * 8 + tg * 2;
                    float2 o2;
                    o2.x = (acc[t][j][2 * h + 0] - mean) * rstd * cbuf[D + col]     + cbuf[2 * D + col];
                    o2.y = (acc[t][j][2 * h + 1] - mean) * rstd * cbuf[D + col + 1] + cbuf[2 * D + col + 1];
                    *(float2*)(out + (size_t)n * D + col) = o2;
                }
            }
        }
    }
}

// ---------------------------------------------------------------------------
extern "C" void kernel_launch(void* const* d_in, const int* in_sizes, int n_in,
                              void* d_out, int out_size) {
    const float* x     = (const float*)d_in[0];
    const int*   ei    = (const int*)d_in[1];
    const float* Ws    = (const float*)d_in[2];
    const float* Wn    = (const float*)d_in[3];
    const float* bias  = (const float*)d_in[4];
    const float* gamma = (const float*)d_in[5];
    const float* beta  = (const float*)d_in[6];
    float*       out   = (float*)d_out;

    size_t smem = (size_t)(MB * 2 * PA2 + 64 * 2 * PB2 + MB * 8 + 3 * D) * sizeof(float); // 105,984 B
    cudaFuncSetAttribute(fused_kernel,
                         cudaFuncAttributeMaxDynamicSharedMemorySize, (int)smem);

    zero_kernel<<<(NN + 511) / 512, 512>>>();
    fill_kernel<<<(EE + 255) / 256, 256>>>(ei);
    gather_kernel<<<(NN * 32 + 255) / 256, 256>>>(x);

    int grid = (NN + MB - 1) / MB;   // 1563
    fused_kernel<<<grid, 256, smem>>>(x, Ws, Wn, bias, gamma, beta, out);
}

// round 7
// speedup vs baseline: 1.3577x; 1.0020x over previous
#include <cuda_runtime.h>
#include <cstdint>

#define NN 100000
#define EE 800000
#define D  128
#define MB 64        // nodes per block (fused kernel)
#define PA2 68       // A pitch in float2 (64 + 4 pad): frag banks g*4+tg
#define PB2 132      // B pitch in float2 (128 + 4 pad): frag banks tg*4+g
#define CAP 48
#define EPSF 1e-5f

// Scratch (__device__ globals; allocation-free rule)
__device__ int g_cnt[NN];
__device__ __align__(16) int g_csr[(size_t)NN * CAP];
__device__ __align__(16) float g_mean[(size_t)NN * D];

// ---------------------------------------------------------------------------
__global__ void zero_kernel() {
    int i = blockIdx.x * blockDim.x + threadIdx.x;
    if (i < NN) g_cnt[i] = 0;
}

__global__ __launch_bounds__(256) void fill_kernel(const int* __restrict__ ei) {
    int e = blockIdx.x * 256 + threadIdx.x;
    if (e >= EE) return;
    int s = ei[e];
    int d = ei[EE + e];
    int p = atomicAdd(&g_cnt[d], 1);
    if (p < CAP) g_csr[(size_t)d * CAP + p] = s;
}

__global__ __launch_bounds__(256) void gather_kernel(const float* __restrict__ x) {
    int n    = (blockIdx.x * 256 + threadIdx.x) >> 5;
    int lane = threadIdx.x & 31;
    if (n >= NN) return;

    int cnt = g_cnt[n];
    int m   = min(cnt, CAP);
    const float4* x4  = (const float4*)x;
    const int*    lst = g_csr + (size_t)n * CAP;

    float4 a = make_float4(0.f, 0.f, 0.f, 0.f);
    int j = 0;
    for (; j + 4 <= m; j += 4) {
        int4 s4 = *(const int4*)(lst + j);
        float4 v0 = x4[(size_t)s4.x * 32 + lane];
        float4 v1 = x4[(size_t)s4.y * 32 + lane];
        float4 v2 = x4[(size_t)s4.z * 32 + lane];
        float4 v3 = x4[(size_t)s4.w * 32 + lane];
        a.x += (v0.x + v1.x) + (v2.x + v3.x);
        a.y += (v0.y + v1.y) + (v2.y + v3.y);
        a.z += (v0.z + v1.z) + (v2.z + v3.z);
        a.w += (v0.w + v1.w) + (v2.w + v3.w);
    }
    for (; j < m; j++) {
        float4 v = x4[(size_t)lst[j] * 32 + lane];
        a.x += v.x; a.y += v.y; a.z += v.z; a.w += v.w;
    }
    float r = 1.f / fmaxf((float)cnt, 1.f);
    a.x *= r; a.y *= r; a.z *= r; a.w *= r;
    ((float4*)g_mean)[(size_t)n * 32 + lane] = a;
}

// ---------------------------------------------------------------------------
__device__ __forceinline__ uint32_t f2tf32(float f) {
    uint32_t r;
    asm("cvt.rna.tf32.f32 %0, %1;" : "=r"(r) : "f"(f));
    return r;
}

extern __shared__ float smem_f[];

// smem layout (floats):
//   Ap : 64 rows x 136  (pairs (k,k+4) as float2, pitch PA2=68 f2)   8704
//   Bp : 64 pr   x 264  (pr = ks*4+tg; pairs (k,k+4); pitch 132 f2) 16896
//   red_s[64][4], red_s2[64][4], cbuf[384]
__global__ __launch_bounds__(256, 2) void fused_kernel(
    const float* __restrict__ x,  const float* __restrict__ Ws,
    const float* __restrict__ Wn, const float* __restrict__ bias,
    const float* __restrict__ gamma, const float* __restrict__ beta,
    float* __restrict__ out)
{
    float* Ap     = smem_f;
    float* Bp     = Ap + MB * (2 * PA2);       // 8704
    float* red_s  = Bp + 64 * (2 * PB2);       // +16896
    float* red_s2 = red_s + MB * 4;
    float* cbuf   = red_s2 + MB * 4;

    const int tid  = threadIdx.x;
    const int base = blockIdx.x * MB;
    const int lane = tid & 31;
    const int wid  = tid >> 5;
    const int wm   = wid & 1;        // row half: wm*32
    const int wn   = wid >> 1;       // col quarter: wn*32
    const int g    = lane >> 2;      // 0..7
    const int tg   = lane & 3;       // 0..3

    if (tid < D) {
        cbuf[tid]         = bias[tid];
        cbuf[D + tid]     = gamma[tid];
        cbuf[2 * D + tid] = beta[tid];
    }

    // Staging decompositions (pair-interleaved writes, coalesced reads)
    const int a_rl = tid & 7;           // row low
    const int a_cl = (tid >> 3) & 3;    // c low (float4 index)
    const int a_rg = tid >> 5;          // row mid (0..7)

    float acc[2][4][4];
    #pragma unroll
    for (int t = 0; t < 2; t++)
        #pragma unroll
        for (int j = 0; j < 4; j++)
            #pragma unroll
            for (int e = 0; e < 4; e++) acc[t][j][e] = 0.f;

    const float2* Ap2 = (const float2*)Ap;
    const float2* Bp2 = (const float2*)Bp;

    #pragma unroll 1
    for (int phase = 0; phase < 2; phase++) {
        if (phase == 1) __syncthreads();   // MMA reads of phase 0 done

        // ---- stage A tile (x or mean), tf32, pair-interleaved ----
        const float4* src4 = phase ? (const float4*)g_mean : (const float4*)x;
        #pragma unroll
        for (int it = 0; it < 8; it++) {
            int row = a_rl + 8 * a_rg;
            int c   = a_cl + 4 * it;
            int n   = base + row;
            float4 v = make_float4(0.f, 0.f, 0.f, 0.f);
            if (n < NN) v = src4[(size_t)n * 32 + c];
            int prb = (c >> 1) * 4;      // pair-row base
            int sl  = c & 1;             // slot within float2
            float* dst = Ap + row * (2 * PA2);
            dst[(prb + 0) * 2 + sl] = __uint_as_float(f2tf32(v.x));
            dst[(prb + 1) * 2 + sl] = __uint_as_float(f2tf32(v.y));
            dst[(prb + 2) * 2 + sl] = __uint_as_float(f2tf32(v.z));
            dst[(prb + 3) * 2 + sl] = __uint_as_float(f2tf32(v.w));
        }

        // ---- stage B (Ws or Wn), tf32, pair-interleaved: Bp[pr][col] ----
        const float4* W4 = (const float4*)(phase ? Wn : Ws);
        #pragma unroll
        for (int it = 0; it < 16; it++) {
            int col = a_rl + 8 * a_rg + 64 * (it >> 3);
            int c   = a_cl + 4 * (it & 7);
            float4 v = W4[(size_t)col * 32 + c];
            int prb = (c >> 1) * 4;
            int sl  = c & 1;
            float* dst = Bp + col * 2 + sl;
            dst[(prb + 0) * (2 * PB2)] = __uint_as_float(f2tf32(v.x));
            dst[(prb + 1) * (2 * PB2)] = __uint_as_float(f2tf32(v.y));
            dst[(prb + 2) * (2 * PB2)] = __uint_as_float(f2tf32(v.z));
            dst[(prb + 3) * (2 * PB2)] = __uint_as_float(f2tf32(v.w));
        }
        __syncthreads();

        // ---- MMA mainloop: 16 k-steps, 8 LDS.64 + 8 MMA each ----
        #pragma unroll
        for (int ks = 0; ks < 16; ks++) {
            float2 bb[4];
            #pragma unroll
            for (int j = 0; j < 4; j++)
                bb[j] = Bp2[(ks * 4 + tg) * PB2 + wn * 32 + j * 8 + g];
            #pragma unroll
            for (int t = 0; t < 2; t++) {
                const int r0 = wm * 32 + t * 16 + g;
                float2 a02 = Ap2[r0 * PA2       + ks * 4 + tg];
                float2 a13 = Ap2[(r0 + 8) * PA2 + ks * 4 + tg];
                uint32_t ua0 = __float_as_uint(a02.x);
                uint32_t ua1 = __float_as_uint(a13.x);
                uint32_t ua2 = __float_as_uint(a02.y);
                uint32_t ua3 = __float_as_uint(a13.y);
                #pragma unroll
                for (int j = 0; j < 4; j++) {
                    asm volatile(
                        "mma.sync.aligned.m16n8k8.row.col.f32.tf32.tf32.f32 "
                        "{%0,%1,%2,%3}, {%4,%5,%6,%7}, {%8,%9}, {%0,%1,%2,%3};"
                        : "+f"(acc[t][j][0]), "+f"(acc[t][j][1]),
                          "+f"(acc[t][j][2]), "+f"(acc[t][j][3])
                        : "r"(ua0), "r"(ua1), "r"(ua2), "r"(ua3),
                          "r"(__float_as_uint(bb[j].x)), "r"(__float_as_uint(bb[j].y)));
                }
            }
        }
    }

    // ---- Epilogue: bias + ReLU + LayerNorm ----
    #pragma unroll
    for (int t = 0; t < 2; t++) {
        #pragma unroll
        for (int h = 0; h < 2; h++) {
            float s = 0.f, s2 = 0.f;
            #pragma unroll
            for (int j = 0; j < 4; j++) {
                #pragma unroll
                for (int e = 0; e < 2; e++) {
                    int col = wn * 32 + j * 8 + tg * 2 + e;
                    float v = fmaxf(acc[t][j][2 * h + e] + cbuf[col], 0.f);
                    acc[t][j][2 * h + e] = v;
                    s += v; s2 += v * v;
                }
            }
            s  += __shfl_xor_sync(0xffffffffu, s, 1);
            s  += __shfl_xor_sync(0xffffffffu, s, 2);
            s2 += __shfl_xor_sync(0xffffffffu, s2, 1);
            s2 += __shfl_xor_sync(0xffffffffu, s2, 2);
            if (tg == 0) {
                int row = wm * 32 + t * 16 + h * 8 + g;
                red_s [row * 4 + wn] = s;
                red_s2[row * 4 + wn] = s2;
            }
        }
    }
    __syncthreads();

    #pragma unroll
    for (int t = 0; t < 2; t++) {
        #pragma unroll
        for (int h = 0; h < 2; h++) {
            int row = wm * 32 + t * 16 + h * 8 + g;
            float s  = red_s [row * 4] + red_s [row * 4 + 1]
                     + red_s [row * 4 + 2] + red_s [row * 4 + 3];
            float s2 = red_s2[row * 4] + red_s2[row * 4 + 1]
                     + red_s2[row * 4 + 2] + red_s2[row * 4 + 3];
            float mean = s * (1.f / D);
            float var  = s2 * (1.f / D) - mean * mean;
            float rstd = rsqrtf(var + EPSF);
            int n = base + row;
            if (n < NN) {
                #pragma unroll
                for (int j = 0; j < 4; j++) {
                    int col = wn * 32 + j * 8 + tg * 2;
                    float2 o2;
                    o2.x = (acc[t][j][2 * h + 0] - mean) * rstd * cbuf[D + col]     + cbuf[2 * D + col];
                    o2.y = (acc[t][j][2 * h + 1] - mean) * rstd * cbuf[D + col + 1] + cbuf[2 * D + col + 1];
                    *(float2*)(out + (size_t)n * D + col) = o2;
                }
            }
        }
    }
}

// ---------------------------------------------------------------------------
extern "C" void kernel_launch(void* const* d_in, const int* in_sizes, int n_in,
                              void* d_out, int out_size) {
    const float* x     = (const float*)d_in[0];
    const int*   ei    = (const int*)d_in[1];
    const float* Ws    = (const float*)d_in[2];
    const float* Wn    = (const float*)d_in[3];
    const float* bias  = (const float*)d_in[4];
    const float* gamma = (const float*)d_in[5];
    const float* beta  = (const float*)d_in[6];
    float*       out   = (float*)d_out;

    size_t smem = (size_t)(MB * 2 * PA2 + 64 * 2 * PB2 + MB * 8 + 3 * D) * sizeof(float); // 105,984 B
    cudaFuncSetAttribute(fused_kernel,
                         cudaFuncAttributeMaxDynamicSharedMemorySize, (int)smem);

    zero_kernel<<<(NN + 511) / 512, 512>>>();
    fill_kernel<<<(EE + 255) / 256, 256>>>(ei);
    gather_kernel<<<(NN * 32 + 255) / 256, 256>>>(x);

    int grid = (NN + MB - 1) / MB;   // 1563
    fused_kernel<<<grid, 256, smem>>>(x, Ws, Wn, bias, gamma, beta, out);
}

// round 8
// speedup vs baseline: 1.9232x; 1.4165x over previous
#include <cuda_runtime.h>
#include <cstdint>

#define NN 100000
#define EE 800000
#define D  128
#define MB 64        // nodes per block (fused kernel)
#define PA2 68       // A pitch in float2: frag banks 4g+tg (conflict-free)
#define PB2 132      // B pitch in float2: frag banks 4tg+g+8j (conflict-free)
#define CAP 48
#define EPSF 1e-5f
#define WIMG 17408   // floats per weight image (64*264=16896, padded)

// Scratch (__device__ globals; allocation-free rule)
__device__ int g_cnt[NN];
__device__ __align__(16) int g_csr[(size_t)NN * CAP];
__device__ __align__(16) float g_mean[(size_t)NN * D];   // tf32, pair-interleaved rows
__device__ __align__(16) float g_wimg[2 * WIMG];         // tf32 Bp smem images

__device__ __forceinline__ uint32_t f2tf32(float f) {
    uint32_t r;
    asm("cvt.rna.tf32.f32 %0, %1;" : "=r"(r) : "f"(f));
    return r;
}
__device__ __forceinline__ float tff(float f) { return __uint_as_float(f2tf32(f)); }

// ---------------------------------------------------------------------------
__global__ void zero_kernel() {
    int i = blockIdx.x * blockDim.x + threadIdx.x;
    if (i < NN) g_cnt[i] = 0;
}

__global__ __launch_bounds__(256) void fill_kernel(const int* __restrict__ ei) {
    int e = blockIdx.x * 256 + threadIdx.x;
    if (e >= EE) return;
    int s = ei[e];
    int d = ei[EE + e];
    int p = atomicAdd(&g_cnt[d], 1);
    if (p < CAP) g_csr[(size_t)d * CAP + p] = s;
}

// Pre-convert weights to tf32 in the exact padded Bp smem layout:
// img[pr*264 + col*2 + slot] = tf32(W[col][k]),  pr=(k>>3)*4+(k&3), slot=(k>>2)&1
__global__ __launch_bounds__(256) void wprep_kernel(
    const float* __restrict__ Ws, const float* __restrict__ Wn)
{
    int t = blockIdx.x * 256 + threadIdx.x;
    if (t >= 2 * 128 * 32) return;
    int w   = t >> 12;
    int col = (t >> 5) & 127;
    int c   = t & 31;
    const float4* W4 = (const float4*)(w ? Wn : Ws);
    float4 v = W4[col * 32 + c];
    float* img = g_wimg + w * WIMG;
    int prb = (c >> 1) * 4;
    int bi  = col * 2 + (c & 1);
    img[(prb + 0) * 264 + bi] = tff(v.x);
    img[(prb + 1) * 264 + bi] = tff(v.y);
    img[(prb + 2) * 264 + bi] = tff(v.z);
    img[(prb + 3) * 264 + bi] = tff(v.w);
}

// gather: one warp per node; writes mean as tf32 PAIR-INTERLEAVED row
// (pairs (k,k+4) adjacent), so fused staging is a pure memcpy.
__global__ __launch_bounds__(256) void gather_kernel(const float* __restrict__ x) {
    int n    = (blockIdx.x * 256 + threadIdx.x) >> 5;
    int lane = threadIdx.x & 31;
    if (n >= NN) return;

    int cnt = g_cnt[n];
    int m   = min(cnt, CAP);
    const float4* x4  = (const float4*)x;
    const int*    lst = g_csr + (size_t)n * CAP;

    float4 a = make_float4(0.f, 0.f, 0.f, 0.f);
    int j = 0;
    for (; j + 4 <= m; j += 4) {
        int4 s4 = *(const int4*)(lst + j);
        float4 v0 = x4[(size_t)s4.x * 32 + lane];
        float4 v1 = x4[(size_t)s4.y * 32 + lane];
        float4 v2 = x4[(size_t)s4.z * 32 + lane];
        float4 v3 = x4[(size_t)s4.w * 32 + lane];
        a.x += (v0.x + v1.x) + (v2.x + v3.x);
        a.y += (v0.y + v1.y) + (v2.y + v3.y);
        a.z += (v0.z + v1.z) + (v2.z + v3.z);
        a.w += (v0.w + v1.w) + (v2.w + v3.w);
    }
    for (; j < m; j++) {
        float4 v = x4[(size_t)lst[j] * 32 + lane];
        a.x += v.x; a.y += v.y; a.z += v.z; a.w += v.w;
    }
    float r = 1.f / fmaxf((float)cnt, 1.f);
    float4 t;
    t.x = tff(a.x * r); t.y = tff(a.y * r);
    t.z = tff(a.z * r); t.w = tff(a.w * r);
    float4 p;
    p.x = __shfl_xor_sync(0xffffffffu, t.x, 1);
    p.y = __shfl_xor_sync(0xffffffffu, t.y, 1);
    p.z = __shfl_xor_sync(0xffffffffu, t.z, 1);
    p.w = __shfl_xor_sync(0xffffffffu, t.w, 1);
    float4 o = (lane & 1) ? make_float4(p.z, t.z, p.w, t.w)
                          : make_float4(t.x, p.x, t.y, p.y);
    ((float4*)g_mean)[(size_t)n * 32 + lane] = o;
}

// ---------------------------------------------------------------------------
extern __shared__ float smem_f[];

__global__ __launch_bounds__(256, 2) void fused_kernel(
    const float* __restrict__ x, const float* __restrict__ bias,
    const float* __restrict__ gamma, const float* __restrict__ beta,
    float* __restrict__ out)
{
    float* Ap     = smem_f;                    // [64][136] floats
    float* Bp     = Ap + MB * (2 * PA2);       // [64][264] floats
    float* red_s  = Bp + 64 * (2 * PB2);
    float* red_s2 = red_s + MB * 4;
    float* cbuf   = red_s2 + MB * 4;

    const int tid  = threadIdx.x;
    const int base = blockIdx.x * MB;
    const int lane = tid & 31;
    const int wid  = tid >> 5;
    const int wm   = wid & 1;
    const int wn   = wid >> 1;
    const int g    = lane >> 2;
    const int tg   = lane & 3;

    if (tid < D) {
        cbuf[tid]         = bias[tid];
        cbuf[D + tid]     = gamma[tid];
        cbuf[2 * D + tid] = beta[tid];
    }

    float acc[2][4][4];
    #pragma unroll
    for (int t = 0; t < 2; t++)
        #pragma unroll
        for (int j = 0; j < 4; j++)
            #pragma unroll
            for (int e = 0; e < 4; e++) acc[t][j][e] = 0.f;

    const float2* Ap2 = (const float2*)Ap;
    const float2* Bp2 = (const float2*)Bp;
    const int a_row = tid >> 2;
    const int n_row = base + a_row;

    #pragma unroll 1
    for (int phase = 0; phase < 2; phase++) {
        if (phase == 1) __syncthreads();

        if (phase == 0) {
            // x: register pairing + tf32 cvt, 2 LDG.128 + 2 STS.128 per task
            const float4* x4 = (const float4*)x;
            #pragma unroll
            for (int it = 0; it < 4; it++) {
                int cp = (tid & 3) + 4 * it;       // pair-group 0..15
                float4 v0 = make_float4(0.f, 0.f, 0.f, 0.f), v1 = v0;
                if (n_row < NN) {
                    v0 = x4[(size_t)n_row * 32 + 2 * cp];
                    v1 = x4[(size_t)n_row * 32 + 2 * cp + 1];
                }
                float4 s0 = make_float4(tff(v0.x), tff(v1.x), tff(v0.y), tff(v1.y));
                float4 s1 = make_float4(tff(v0.z), tff(v1.z), tff(v0.w), tff(v1.w));
                float* dst = Ap + a_row * (2 * PA2) + cp * 8;
                ((float4*)dst)[0] = s0;
                ((float4*)dst)[1] = s1;
            }
        } else {
            // mean: pure float4 memcpy (pre-paired tf32)
            const float4* m4 = (const float4*)g_mean;
            #pragma unroll
            for (int it = 0; it < 8; it++) {
                int f4i = (tid & 3) + 4 * it;      // 0..31
                float4 v = make_float4(0.f, 0.f, 0.f, 0.f);
                if (n_row < NN) v = m4[(size_t)n_row * 32 + f4i];
                *(float4*)(Ap + a_row * (2 * PA2) + f4i * 4) = v;
            }
        }

        // B: linear float4 memcpy of the pre-built image (conflict-free)
        const float4* wi  = (const float4*)(g_wimg + phase * WIMG);
        float4*       bp4 = (float4*)Bp;
        #pragma unroll
        for (int it = 0; it < 17; it++) {
            int idx = tid + 256 * it;
            if (idx < 4224) bp4[idx] = wi[idx];
        }
        __syncthreads();

        // ---- MMA mainloop: 16 k-steps, 8 LDS.64 + 8 MMA each ----
        #pragma unroll
        for (int ks = 0; ks < 16; ks++) {
            float2 bb[4];
            #pragma unroll
            for (int j = 0; j < 4; j++)
                bb[j] = Bp2[(ks * 4 + tg) * PB2 + wn * 32 + j * 8 + g];
            #pragma unroll
            for (int t = 0; t < 2; t++) {
                const int r0 = wm * 32 + t * 16 + g;
                float2 a02 = Ap2[r0 * PA2       + ks * 4 + tg];
                float2 a13 = Ap2[(r0 + 8) * PA2 + ks * 4 + tg];
                uint32_t ua0 = __float_as_uint(a02.x);
                uint32_t ua1 = __float_as_uint(a13.x);
                uint32_t ua2 = __float_as_uint(a02.y);
                uint32_t ua3 = __float_as_uint(a13.y);
                #pragma unroll
                for (int j = 0; j < 4; j++) {
                    asm volatile(
                        "mma.sync.aligned.m16n8k8.row.col.f32.tf32.tf32.f32 "
                        "{%0,%1,%2,%3}, {%4,%5,%6,%7}, {%8,%9}, {%0,%1,%2,%3};"
                        : "+f"(acc[t][j][0]), "+f"(acc[t][j][1]),
                          "+f"(acc[t][j][2]), "+f"(acc[t][j][3])
                        : "r"(ua0), "r"(ua1), "r"(ua2), "r"(ua3),
                          "r"(__float_as_uint(bb[j].x)), "r"(__float_as_uint(bb[j].y)));
                }
            }
        }
    }

    // ---- Epilogue: bias + ReLU + LayerNorm ----
    #pragma unroll
    for (int t = 0; t < 2; t++) {
        #pragma unroll
        for (int h = 0; h < 2; h++) {
            float s = 0.f, s2 = 0.f;
            #pragma unroll
            for (int j = 0; j < 4; j++) {
                #pragma unroll
                for (int e = 0; e < 2; e++) {
                    int col = wn * 32 + j * 8 + tg * 2 + e;
                    float v = fmaxf(acc[t][j][2 * h + e] + cbuf[col], 0.f);
                    acc[t][j][2 * h + e] = v;
                    s += v; s2 += v * v;
                }
            }
            s  += __shfl_xor_sync(0xffffffffu, s, 1);
            s  += __shfl_xor_sync(0xffffffffu, s, 2);
            s2 += __shfl_xor_sync(0xffffffffu, s2, 1);
            s2 += __shfl_xor_sync(0xffffffffu, s2, 2);
            if (tg == 0) {
                int row = wm * 32 + t * 16 + h * 8 + g;
                red_s [row * 4 + wn] = s;
                red_s2[row * 4 + wn] = s2;
            }
        }
    }
    __syncthreads();

    #pragma unroll
    for (int t = 0; t < 2; t++) {
        #pragma unroll
        for (int h = 0; h < 2; h++) {
            int row = wm * 32 + t * 16 + h * 8 + g;
            float s  = red_s [row * 4] + red_s [row * 4 + 1]
                     + red_s [row * 4 + 2] + red_s [row * 4 + 3];
            float s2 = red_s2[row * 4] + red_s2[row * 4 + 1]
                     + red_s2[row * 4 + 2] + red_s2[row * 4 + 3];
            float mean = s * (1.f / D);
            float var  = s2 * (1.f / D) - mean * mean;
            float rstd = rsqrtf(var + EPSF);
            int n = base + row;
            if (n < NN) {
                #pragma unroll
                for (int j = 0; j < 4; j++) {
                    int col = wn * 32 + j * 8 + tg * 2;
                    float2 o2;
                    o2.x = (acc[t][j][2 * h + 0] - mean) * rstd * cbuf[D + col]     + cbuf[2 * D + col];
                    o2.y = (acc[t][j][2 * h + 1] - mean) * rstd * cbuf[D + col + 1] + cbuf[2 * D + col + 1];
                    *(float2*)(out + (size_t)n * D + col) = o2;
                }
            }
        }
    }
}

// ---------------------------------------------------------------------------
extern "C" void kernel_launch(void* const* d_in, const int* in_sizes, int n_in,
                              void* d_out, int out_size) {
    const float* x     = (const float*)d_in[0];
    const int*   ei    = (const int*)d_in[1];
    const float* Ws    = (const float*)d_in[2];
    const float* Wn    = (const float*)d_in[3];
    const float* bias  = (const float*)d_in[4];
    const float* gamma = (const float*)d_in[5];
    const float* beta  = (const float*)d_in[6];
    float*       out   = (float*)d_out;

    size_t smem = (size_t)(MB * 2 * PA2 + 64 * 2 * PB2 + MB * 8 + 3 * D) * sizeof(float);
    cudaFuncSetAttribute(fused_kernel,
                         cudaFuncAttributeMaxDynamicSharedMemorySize, (int)smem);

    zero_kernel<<<(NN + 511) / 512, 512>>>();
    wprep_kernel<<<32, 256>>>(Ws, Wn);
    fill_kernel<<<(EE + 255) / 256, 256>>>(ei);
    gather_kernel<<<(NN * 32 + 255) / 256, 256>>>(x);

    int grid = (NN + MB - 1) / MB;   // 1563
    fused_kernel<<<grid, 256, smem>>>(x, bias, gamma, beta, out);
}

// round 9
// speedup vs baseline: 2.1863x; 1.1368x over previous
#include <cuda_runtime.h>
#include <cstdint>

#define NN 100000
#define EE 800000
#define D  128
#define MB 64        // nodes per block (fused kernel)
#define PA2 68       // A pitch in float2: frag loads conflict-free
#define PB2 132      // B pitch in float2: frag loads conflict-free
#define CAP 48
#define EPSF 1e-5f
#define WIMG 17408   // floats per weight image (64*264=16896, padded)
#define BCHUNK 2112  // float4 per half-k B chunk (32 pr-rows x 264 floats)

// Scratch (__device__ globals; allocation-free rule)
__device__ int g_cnt[NN];
__device__ __align__(16) int g_csr[(size_t)NN * CAP];
__device__ __align__(16) float g_mean[(size_t)NN * D];   // tf32, pair-interleaved
__device__ __align__(16) float g_wimg[2 * WIMG];         // tf32 Bp smem images

__device__ __forceinline__ uint32_t f2tf32(float f) {
    uint32_t r;
    asm("cvt.rna.tf32.f32 %0, %1;" : "=r"(r) : "f"(f));
    return r;
}
__device__ __forceinline__ float tff(float f) { return __uint_as_float(f2tf32(f)); }

__device__ __forceinline__ void cpa16(uint32_t dst, const void* src) {
    asm volatile("cp.async.cg.shared.global [%0], [%1], 16;" :: "r"(dst), "l"(src));
}
#define CP_COMMIT() asm volatile("cp.async.commit_group;")
#define CP_WAIT(n)  asm volatile("cp.async.wait_group %0;" :: "n"(n))

// ---------------------------------------------------------------------------
// prep: zero degree counters + build tf32 weight images (fused, one launch)
// ---------------------------------------------------------------------------
__global__ __launch_bounds__(512) void prep_kernel(
    const float* __restrict__ Ws, const float* __restrict__ Wn)
{
    int i = blockIdx.x * 512 + threadIdx.x;
    if (i < NN) g_cnt[i] = 0;
    if (i < 2 * 128 * 32) {
        int w   = i >> 12;
        int col = (i >> 5) & 127;
        int c   = i & 31;
        const float4* W4 = (const float4*)(w ? Wn : Ws);
        float4 v = W4[col * 32 + c];
        float* img = g_wimg + w * WIMG;
        int prb = (c >> 1) * 4;
        int bi  = col * 2 + (c & 1);
        img[(prb + 0) * 264 + bi] = tff(v.x);
        img[(prb + 1) * 264 + bi] = tff(v.y);
        img[(prb + 2) * 264 + bi] = tff(v.z);
        img[(prb + 3) * 264 + bi] = tff(v.w);
    }
}

__global__ __launch_bounds__(256) void fill_kernel(const int* __restrict__ ei) {
    int e = blockIdx.x * 256 + threadIdx.x;
    if (e >= EE) return;
    int s = ei[e];
    int d = ei[EE + e];
    int p = atomicAdd(&g_cnt[d], 1);
    if (p < CAP) g_csr[(size_t)d * CAP + p] = s;
}

// gather: one warp per node; writes tf32 pair-interleaved mean rows
__global__ __launch_bounds__(256) void gather_kernel(const float* __restrict__ x) {
    int n    = (blockIdx.x * 256 + threadIdx.x) >> 5;
    int lane = threadIdx.x & 31;
    if (n >= NN) return;

    int cnt = g_cnt[n];
    int m   = min(cnt, CAP);
    const float4* x4  = (const float4*)x;
    const int*    lst = g_csr + (size_t)n * CAP;

    float4 a = make_float4(0.f, 0.f, 0.f, 0.f);
    int j = 0;
    for (; j + 4 <= m; j += 4) {
        int4 s4 = *(const int4*)(lst + j);
        float4 v0 = x4[(size_t)s4.x * 32 + lane];
        float4 v1 = x4[(size_t)s4.y * 32 + lane];
        float4 v2 = x4[(size_t)s4.z * 32 + lane];
        float4 v3 = x4[(size_t)s4.w * 32 + lane];
        a.x += (v0.x + v1.x) + (v2.x + v3.x);
        a.y += (v0.y + v1.y) + (v2.y + v3.y);
        a.z += (v0.z + v1.z) + (v2.z + v3.z);
        a.w += (v0.w + v1.w) + (v2.w + v3.w);
    }
    for (; j < m; j++) {
        float4 v = x4[(size_t)lst[j] * 32 + lane];
        a.x += v.x; a.y += v.y; a.z += v.z; a.w += v.w;
    }
    float r = 1.f / fmaxf((float)cnt, 1.f);
    float4 t;
    t.x = tff(a.x * r); t.y = tff(a.y * r);
    t.z = tff(a.z * r); t.w = tff(a.w * r);
    float4 p;
    p.x = __shfl_xor_sync(0xffffffffu, t.x, 1);
    p.y = __shfl_xor_sync(0xffffffffu, t.y, 1);
    p.z = __shfl_xor_sync(0xffffffffu, t.z, 1);
    p.w = __shfl_xor_sync(0xffffffffu, t.w, 1);
    float4 o = (lane & 1) ? make_float4(p.z, t.z, p.w, t.w)
                          : make_float4(t.x, p.x, t.y, p.y);
    ((float4*)g_mean)[(size_t)n * 32 + lane] = o;
}

// ---------------------------------------------------------------------------
extern __shared__ float smem_f[];

// One 8-kstep MMA segment: B from half-k buffer (local pr), A full-K resident.
__device__ __forceinline__ void mma_seg(
    const float2* __restrict__ Ap2, const float2* __restrict__ Bb2,
    int ksA, int wm, int wn, int g, int tg, float acc[2][4][4])
{
    #pragma unroll
    for (int ksl = 0; ksl < 8; ksl++) {
        float2 bb[4];
        #pragma unroll
        for (int j = 0; j < 4; j++)
            bb[j] = Bb2[(ksl * 4 + tg) * PB2 + wn * 32 + j * 8 + g];
        const int ks = ksA + ksl;
        #pragma unroll
        for (int t = 0; t < 2; t++) {
            const int r0 = wm * 32 + t * 16 + g;
            float2 a02 = Ap2[r0 * PA2       + ks * 4 + tg];
            float2 a13 = Ap2[(r0 + 8) * PA2 + ks * 4 + tg];
            uint32_t ua0 = __float_as_uint(a02.x);
            uint32_t ua1 = __float_as_uint(a13.x);
            uint32_t ua2 = __float_as_uint(a02.y);
            uint32_t ua3 = __float_as_uint(a13.y);
            #pragma unroll
            for (int j = 0; j < 4; j++) {
                asm volatile(
                    "mma.sync.aligned.m16n8k8.row.col.f32.tf32.tf32.f32 "
                    "{%0,%1,%2,%3}, {%4,%5,%6,%7}, {%8,%9}, {%0,%1,%2,%3};"
                    : "+f"(acc[t][j][0]), "+f"(acc[t][j][1]),
                      "+f"(acc[t][j][2]), "+f"(acc[t][j][3])
                    : "r"(ua0), "r"(ua1), "r"(ua2), "r"(ua3),
                      "r"(__float_as_uint(bb[j].x)), "r"(__float_as_uint(bb[j].y)));
            }
        }
    }
}

__global__ __launch_bounds__(256, 2) void fused_kernel(
    const float* __restrict__ x, const float* __restrict__ bias,
    const float* __restrict__ gamma, const float* __restrict__ beta,
    float* __restrict__ out)
{
    float* Ap     = smem_f;                    // [64][136]      8704 fl
    float* B0     = Ap + MB * (2 * PA2);       // [32 pr][264]   8448 fl
    float* B1     = B0 + 32 * (2 * PB2);       //                8448 fl
    float* red_s  = B1 + 32 * (2 * PB2);
    float* red_s2 = red_s + MB * 4;
    float* cbuf   = red_s2 + MB * 4;

    const int tid  = threadIdx.x;
    const int base = blockIdx.x * MB;
    const int lane = tid & 31;
    const int wid  = tid >> 5;
    const int wm   = wid & 1;
    const int wn   = wid >> 1;
    const int g    = lane >> 2;
    const int tg   = lane & 3;

    if (tid < D) {
        cbuf[tid]         = bias[tid];
        cbuf[D + tid]     = gamma[tid];
        cbuf[2 * D + tid] = beta[tid];
    }

    const uint32_t b0a = (uint32_t)__cvta_generic_to_shared(B0);
    const uint32_t b1a = (uint32_t)__cvta_generic_to_shared(B1);
    const float4* ws4 = (const float4*)g_wimg;            // Ws image
    const float4* wn4 = (const float4*)(g_wimg + WIMG);   // Wn image

    // ---- Prologue: async-copy both Ws half-k chunks; stage x tile ----
    #pragma unroll
    for (int it = 0; it < 9; it++) {
        int idx = tid + 256 * it;
        if (idx < BCHUNK) cpa16(b0a + idx * 16, ws4 + idx);
    }
    CP_COMMIT();                                           // g0: Ws k0
    #pragma unroll
    for (int it = 0; it < 9; it++) {
        int idx = tid + 256 * it;
        if (idx < BCHUNK) cpa16(b1a + idx * 16, ws4 + BCHUNK + idx);
    }
    CP_COMMIT();                                           // g1: Ws k1

    const int a_row = tid >> 2;
    const int n_row = base + a_row;
    {   // x staging: register tf32 cvt, pair-interleaved
        const float4* x4 = (const float4*)x;
        #pragma unroll
        for (int it = 0; it < 4; it++) {
            int cp = (tid & 3) + 4 * it;
            float4 v0 = make_float4(0.f, 0.f, 0.f, 0.f), v1 = v0;
            if (n_row < NN) {
                v0 = x4[(size_t)n_row * 32 + 2 * cp];
                v1 = x4[(size_t)n_row * 32 + 2 * cp + 1];
            }
            float4 s0 = make_float4(tff(v0.x), tff(v1.x), tff(v0.y), tff(v1.y));
            float4 s1 = make_float4(tff(v0.z), tff(v1.z), tff(v0.w), tff(v1.w));
            float* dst = Ap + a_row * (2 * PA2) + cp * 8;
            ((float4*)dst)[0] = s0;
            ((float4*)dst)[1] = s1;
        }
    }

    float acc[2][4][4];
    #pragma unroll
    for (int t = 0; t < 2; t++)
        #pragma unroll
        for (int j = 0; j < 4; j++)
            #pragma unroll
            for (int e = 0; e < 4; e++) acc[t][j][e] = 0.f;

    const float2* Ap2 = (const float2*)Ap;
    const float2* B02 = (const float2*)B0;
    const float2* B12 = (const float2*)B1;

    CP_WAIT(1);            // g0 landed
    __syncthreads();

    // ---- S0: Ws x k[0:64) ----
    mma_seg(Ap2, B02, 0, wm, wn, g, tg, acc);
    __syncthreads();       // B0 free

    // refill B0 with Wn k0 (overlaps S1)
    #pragma unroll
    for (int it = 0; it < 9; it++) {
        int idx = tid + 256 * it;
        if (idx < BCHUNK) cpa16(b0a + idx * 16, wn4 + idx);
    }
    CP_COMMIT();                                           // g2: Wn k0

    // prefetch mean rows into registers (lands during S1)
    float4 mv[8];
    {
        const float4* m4 = (const float4*)g_mean;
        #pragma unroll
        for (int it = 0; it < 8; it++) {
            int f4i = (tid & 3) + 4 * it;
            mv[it] = (n_row < NN) ? m4[(size_t)n_row * 32 + f4i]
                                  : make_float4(0.f, 0.f, 0.f, 0.f);
        }
    }

    CP_WAIT(1);            // g1 landed (g2 may still fly)
    __syncthreads();

    // ---- S1: Ws x k[64:128) ----
    mma_seg(Ap2, B12, 8, wm, wn, g, tg, acc);
    __syncthreads();       // B1 + Ap free

    // refill B1 with Wn k1 (overlaps S2); swap A tile to mean
    #pragma unroll
    for (int it = 0; it < 9; it++) {
        int idx = tid + 256 * it;
        if (idx < BCHUNK) cpa16(b1a + idx * 16, wn4 + BCHUNK + idx);
    }
    CP_COMMIT();                                           // g3: Wn k1
    #pragma unroll
    for (int it = 0; it < 8; it++) {
        int f4i = (tid & 3) + 4 * it;
        *(float4*)(Ap + a_row * (2 * PA2) + f4i * 4) = mv[it];
    }

    CP_WAIT(1);            // g2 landed
    __syncthreads();

    // ---- S2: Wn x k[0:64) ----
    mma_seg(Ap2, B02, 0, wm, wn, g, tg, acc);

    CP_WAIT(0);            // g3 landed
    __syncthreads();

    // ---- S3: Wn x k[64:128) ----
    mma_seg(Ap2, B12, 8, wm, wn, g, tg, acc);

    // ---- Epilogue: bias + ReLU + LayerNorm ----
    #pragma unroll
    for (int t = 0; t < 2; t++) {
        #pragma unroll
        for (int h = 0; h < 2; h++) {
            float s = 0.f, s2 = 0.f;
            #pragma unroll
            for (int j = 0; j < 4; j++) {
                #pragma unroll
                for (int e = 0; e < 2; e++) {
                    int col = wn * 32 + j * 8 + tg * 2 + e;
                    float v = fmaxf(acc[t][j][2 * h + e] + cbuf[col], 0.f);
                    acc[t][j][2 * h + e] = v;
                    s += v; s2 += v * v;
                }
            }
            s  += __shfl_xor_sync(0xffffffffu, s, 1);
            s  += __shfl_xor_sync(0xffffffffu, s, 2);
            s2 += __shfl_xor_sync(0xffffffffu, s2, 1);
            s2 += __shfl_xor_sync(0xffffffffu, s2, 2);
            if (tg == 0) {
                int row = wm * 32 + t * 16 + h * 8 + g;
                red_s [row * 4 + wn] = s;
                red_s2[row * 4 + wn] = s2;
            }
        }
    }
    __syncthreads();

    #pragma unroll
    for (int t = 0; t < 2; t++) {
        #pragma unroll
        for (int h = 0; h < 2; h++) {
            int row = wm * 32 + t * 16 + h * 8 + g;
            float s  = red_s [row * 4] + red_s [row * 4 + 1]
                     + red_s [row * 4 + 2] + red_s [row * 4 + 3];
            float s2 = red_s2[row * 4] + red_s2[row * 4 + 1]
                     + red_s2[row * 4 + 2] + red_s2[row * 4 + 3];
            float mean = s * (1.f / D);
            float var  = s2 * (1.f / D) - mean * mean;
            float rstd = rsqrtf(var + EPSF);
            int n = base + row;
            if (n < NN) {
                #pragma unroll
                for (int j = 0; j < 4; j++) {
                    int col = wn * 32 + j * 8 + tg * 2;
                    float2 o2;
                    o2.x = (acc[t][j][2 * h + 0] - mean) * rstd * cbuf[D + col]     + cbuf[2 * D + col];
                    o2.y = (acc[t][j][2 * h + 1] - mean) * rstd * cbuf[D + col + 1] + cbuf[2 * D + col + 1];
                    *(float2*)(out + (size_t)n * D + col) = o2;
                }
            }
        }
    }
}

// ---------------------------------------------------------------------------
extern "C" void kernel_launch(void* const* d_in, const int* in_sizes, int n_in,
                              void* d_out, int out_size) {
    const float* x     = (const float*)d_in[0];
    const int*   ei    = (const int*)d_in[1];
    const float* Ws    = (const float*)d_in[2];
    const float* Wn    = (const float*)d_in[3];
    const float* bias  = (const float*)d_in[4];
    const float* gamma = (const float*)d_in[5];
    const float* beta  = (const float*)d_in[6];
    float*       out   = (float*)d_out;

    size_t smem = (size_t)(MB * 2 * PA2 + 2 * 32 * 2 * PB2 + MB * 8 + 3 * D) * sizeof(float);
    cudaFuncSetAttribute(fused_kernel,
                         cudaFuncAttributeMaxDynamicSharedMemorySize, (int)smem);

    prep_kernel<<<(NN + 511) / 512, 512>>>(Ws, Wn);
    fill_kernel<<<(EE + 255) / 256, 256>>>(ei);
    gather_kernel<<<(NN * 32 + 255) / 256, 256>>>(x);

    int grid = (NN + MB - 1) / MB;   // 1563
    fused_kernel<<<grid, 256, smem>>>(x, bias, gamma, beta, out);
}